// round 7
// baseline (speedup 1.0000x reference)
#include <cuda_runtime.h>
#include <cuda_fp16.h>
#include <math.h>

#define N_USERS 100000
#define M_ITEMS 50000
#define N_ALL   150000
#define N_EDGES 4800000
#define DIM     64
#define NF2     (DIM / 2)           // 32 half2/float2 per row
#define NF4     (DIM / 4)
#define TOT_F2  (N_ALL * NF2)
#define TOT_F4  (N_ALL * NF4)

#define SCAN_BLK 1024
#define N_SCAN_BLOCKS ((N_ALL + SCAN_BLK - 1) / SCAN_BLK)   // 147

// ---- scratch (static device globals; no runtime allocation) ----
__device__ int     g_cnt[N_ALL];
__device__ int     g_off[N_ALL + 1];
__device__ int     g_cur[N_ALL];
__device__ int     g_bsums[256];
__device__ int2    g_edges[N_EDGES];       // packed (col, val-as-int)
__device__ float2  g_E0[TOT_F2];           // fp32 levels (exact recurrence)
__device__ float2  g_E1[TOT_F2];
__device__ float2  g_E2[TOT_F2];
__device__ __half2 g_H0[TOT_F2];           // fp16 shadows (gather sources)
__device__ __half2 g_H1[TOT_F2];
__device__ __half2 g_H2[TOT_F2];

// ---------------------------------------------------------------------------
// E0 = concat(user_emb, item_emb) fp32 + fp16 shadow; zero degree counters
// ---------------------------------------------------------------------------
__global__ void concat_zero_kernel(const float4* __restrict__ u,
                                   const float4* __restrict__ it) {
    int i = blockIdx.x * blockDim.x + threadIdx.x;
    if (i < N_ALL) g_cnt[i] = 0;
    if (i >= TOT_F4) return;
    const int NU = N_USERS * NF4;
    float4 v = (i < NU) ? u[i] : it[i - NU];
    ((float4*)g_E0)[i] = v;
    g_H0[2 * i]     = __floats2half2_rn(v.x, v.y);
    g_H0[2 * i + 1] = __floats2half2_rn(v.z, v.w);
}

// ---------------------------------------------------------------------------
// CSR build: histogram -> 2-level exclusive scan -> scatter
// ---------------------------------------------------------------------------
__global__ void hist_kernel(const int* __restrict__ rows) {
    int e = blockIdx.x * blockDim.x + threadIdx.x;
    if (e >= N_EDGES) return;
    atomicAdd(&g_cnt[rows[e]], 1);
}

__global__ void scan1_kernel() {
    __shared__ int sh[SCAN_BLK];
    int t = threadIdx.x;
    int g = blockIdx.x * SCAN_BLK + t;
    int v = (g < N_ALL) ? g_cnt[g] : 0;
    sh[t] = v;
    __syncthreads();
    #pragma unroll
    for (int d = 1; d < SCAN_BLK; d <<= 1) {
        int add = (t >= d) ? sh[t - d] : 0;
        __syncthreads();
        sh[t] += add;
        __syncthreads();
    }
    if (g < N_ALL) g_off[g] = sh[t] - v;
    if (t == SCAN_BLK - 1) g_bsums[blockIdx.x] = sh[t];
}

__global__ void scan2_kernel() {                    // 1 block, 256 threads
    __shared__ int sh[256];
    int t = threadIdx.x;
    int v = (t < N_SCAN_BLOCKS) ? g_bsums[t] : 0;
    sh[t] = v;
    __syncthreads();
    #pragma unroll
    for (int d = 1; d < 256; d <<= 1) {
        int add = (t >= d) ? sh[t - d] : 0;
        __syncthreads();
        sh[t] += add;
        __syncthreads();
    }
    g_bsums[t] = sh[t] - v;
}

__global__ void add_off_kernel() {
    int g = blockIdx.x * blockDim.x + threadIdx.x;
    if (g >= N_ALL) return;
    int o = g_off[g] + g_bsums[g / SCAN_BLK];
    g_off[g] = o;
    g_cur[g] = o;
    if (g == 0) g_off[N_ALL] = N_EDGES;
}

__global__ void scatter_kernel(const int*   __restrict__ rows,
                               const int*   __restrict__ cols,
                               const float* __restrict__ vals) {
    int e = blockIdx.x * blockDim.x + threadIdx.x;
    if (e >= N_EDGES) return;
    int p = atomicAdd(&g_cur[rows[e]], 1);
    g_edges[p] = make_int2(cols[e], __float_as_int(vals[e]));
}

// ---------------------------------------------------------------------------
// Warp-per-row CSR SpMM over the fp16 shadow, fp32 accumulation.
// Meta: 1 coalesced LDG.64 per 32 edges (lane l holds edge base+l), broadcast
// via shfl. Gather: 1 warp-wide LDG.32 (half2/lane = 128B row), 8 in flight.
// ---------------------------------------------------------------------------
__device__ __forceinline__ void spmm_row_acc(const __half2* __restrict__ src,
                                             int s, int e, int lane,
                                             float2& acc) {
    float2 a0 = make_float2(0.f, 0.f);
    float2 a1 = make_float2(0.f, 0.f);
    float2 a2 = make_float2(0.f, 0.f);
    float2 a3 = make_float2(0.f, 0.f);
    const unsigned FULL = 0xffffffffu;

    for (int base = s; base < e; base += 32) {
        int cnt = e - base;
        if (cnt > 32) cnt = 32;
        int2 my = make_int2(0, 0);
        if (lane < cnt) my = __ldg(&g_edges[base + lane]);

        int j = 0;
        for (; j + 7 < cnt; j += 8) {
            int c0 = __shfl_sync(FULL, my.x, j);
            int c1 = __shfl_sync(FULL, my.x, j + 1);
            int c2 = __shfl_sync(FULL, my.x, j + 2);
            int c3 = __shfl_sync(FULL, my.x, j + 3);
            int c4 = __shfl_sync(FULL, my.x, j + 4);
            int c5 = __shfl_sync(FULL, my.x, j + 5);
            int c6 = __shfl_sync(FULL, my.x, j + 6);
            int c7 = __shfl_sync(FULL, my.x, j + 7);
            __half2 h0 = __ldg(src + (unsigned)c0 * NF2 + lane);
            __half2 h1 = __ldg(src + (unsigned)c1 * NF2 + lane);
            __half2 h2 = __ldg(src + (unsigned)c2 * NF2 + lane);
            __half2 h3 = __ldg(src + (unsigned)c3 * NF2 + lane);
            __half2 h4 = __ldg(src + (unsigned)c4 * NF2 + lane);
            __half2 h5 = __ldg(src + (unsigned)c5 * NF2 + lane);
            __half2 h6 = __ldg(src + (unsigned)c6 * NF2 + lane);
            __half2 h7 = __ldg(src + (unsigned)c7 * NF2 + lane);
            float v0 = __int_as_float(__shfl_sync(FULL, my.y, j));
            float v1 = __int_as_float(__shfl_sync(FULL, my.y, j + 1));
            float v2 = __int_as_float(__shfl_sync(FULL, my.y, j + 2));
            float v3 = __int_as_float(__shfl_sync(FULL, my.y, j + 3));
            float v4 = __int_as_float(__shfl_sync(FULL, my.y, j + 4));
            float v5 = __int_as_float(__shfl_sync(FULL, my.y, j + 5));
            float v6 = __int_as_float(__shfl_sync(FULL, my.y, j + 6));
            float v7 = __int_as_float(__shfl_sync(FULL, my.y, j + 7));
            float2 x0 = __half22float2(h0);
            float2 x1 = __half22float2(h1);
            float2 x2 = __half22float2(h2);
            float2 x3 = __half22float2(h3);
            a0.x += v0 * x0.x; a0.y += v0 * x0.y;
            a1.x += v1 * x1.x; a1.y += v1 * x1.y;
            a2.x += v2 * x2.x; a2.y += v2 * x2.y;
            a3.x += v3 * x3.x; a3.y += v3 * x3.y;
            float2 x4 = __half22float2(h4);
            float2 x5 = __half22float2(h5);
            float2 x6 = __half22float2(h6);
            float2 x7 = __half22float2(h7);
            a0.x += v4 * x4.x; a0.y += v4 * x4.y;
            a1.x += v5 * x5.x; a1.y += v5 * x5.y;
            a2.x += v6 * x6.x; a2.y += v6 * x6.y;
            a3.x += v7 * x7.x; a3.y += v7 * x7.y;
        }
        for (; j < cnt; j++) {
            int c = __shfl_sync(FULL, my.x, j);
            float v = __int_as_float(__shfl_sync(FULL, my.y, j));
            float2 x = __half22float2(__ldg(src + (unsigned)c * NF2 + lane));
            a0.x += v * x.x; a0.y += v * x.y;
        }
    }
    acc.x = (a0.x + a1.x) + (a2.x + a3.x);
    acc.y = (a0.y + a1.y) + (a2.y + a3.y);
}

// dst = th1*spmm(srcH) - th3*prev  (fp32) + fp16 shadow of dst
__global__ __launch_bounds__(256)
void spmm_csr_kernel(const __half2* __restrict__ srcH,
                     const float2*  __restrict__ prev,
                     float2*        __restrict__ dst,
                     __half2*       __restrict__ dstH,
                     float th1, float th3) {
    int w    = (blockIdx.x * blockDim.x + threadIdx.x) >> 5;
    int lane = threadIdx.x & 31;
    if (w >= N_ALL) return;
    int s = __ldg(&g_off[w]);
    int e = __ldg(&g_off[w + 1]);
    float2 acc;
    spmm_row_acc(srcH, s, e, lane, acc);
    float2 p = __ldg(prev + w * NF2 + lane);
    float2 r = make_float2(th1 * acc.x - th3 * p.x,
                           th1 * acc.y - th3 * p.y);
    dst[w * NF2 + lane]  = r;
    dstH[w * NF2 + lane] = __floats2half2_rn(r.x, r.y);
}

// Last pass: e3 on the fly, fused band_stop/band_pass epilogue
__global__ __launch_bounds__(256)
void spmm_final_kernel(float2* __restrict__ out, float th1, float th3) {
    int w    = (blockIdx.x * blockDim.x + threadIdx.x) >> 5;
    int lane = threadIdx.x & 31;
    if (w >= N_ALL) return;
    int s = __ldg(&g_off[w]);
    int e = __ldg(&g_off[w + 1]);
    float2 acc;
    spmm_row_acc(g_H2, s, e, lane, acc);

    float2 e0 = __ldg(g_E0 + w * NF2 + lane);
    float2 e1 = __ldg(g_E1 + w * NF2 + lane);
    float2 e2 = __ldg(g_E2 + w * NF2 + lane);
    float2 e3 = make_float2(th1 * acc.x - th3 * e1.x,
                            th1 * acc.y - th3 * e1.y);
    float2 bs = make_float2(0.25f * (e0.x + e1.x + e2.x + e3.x),
                            0.25f * (e0.y + e1.y + e2.y + e3.y));
    float2 bp = make_float2(tanhf(0.1f * e0.x - bs.x),
                            tanhf(0.1f * e0.y - bs.y));
    out[w * 64 + lane]      = bs;
    out[w * 64 + 32 + lane] = bp;
}

// ---------------------------------------------------------------------------
extern "C" void kernel_launch(void* const* d_in, const int* in_sizes, int n_in,
                              void* d_out, int out_size) {
    const float4* u    = (const float4*)d_in[0];
    const float4* it   = (const float4*)d_in[1];
    const int*    rows = (const int*)  d_in[2];
    const int*    cols = (const int*)  d_in[3];
    const float*  vals = (const float*)d_in[4];
    float2* out = (float2*)d_out;

    float2 *E0, *E1, *E2;
    __half2 *H0, *H1, *H2;
    cudaGetSymbolAddress((void**)&E0, g_E0);
    cudaGetSymbolAddress((void**)&E1, g_E1);
    cudaGetSymbolAddress((void**)&E2, g_E2);
    cudaGetSymbolAddress((void**)&H0, g_H0);
    cudaGetSymbolAddress((void**)&H1, g_H1);
    cudaGetSymbolAddress((void**)&H2, g_H2);

    const int TPB = 256;
    const int ELEM_BLKS = (TOT_F4 + TPB - 1) / TPB;
    const int EDGE_BLKS = (N_EDGES + TPB - 1) / TPB;
    const int NODE_BLKS = (N_ALL + TPB - 1) / TPB;
    const int SPMM_BLKS = (N_ALL * 32 + TPB - 1) / TPB;   // warp per row

    // Jacobi(1,1) coefficients
    const float TH1_2 = 1.875f;
    const float TH3_2 = 0.75f;
    const float TH1_3 = 56.0f / 30.0f;
    const float TH3_3 = 0.8f;

    concat_zero_kernel<<<ELEM_BLKS, TPB>>>(u, it);

    hist_kernel<<<EDGE_BLKS, TPB>>>(rows);
    scan1_kernel<<<N_SCAN_BLOCKS, SCAN_BLK>>>();
    scan2_kernel<<<1, 256>>>();
    add_off_kernel<<<NODE_BLKS, TPB>>>();
    scatter_kernel<<<EDGE_BLKS, TPB>>>(rows, cols, vals);

    spmm_csr_kernel<<<SPMM_BLKS, TPB>>>(H0, E0, E1, H1, 1.0f, 0.0f);
    spmm_csr_kernel<<<SPMM_BLKS, TPB>>>(H1, E0, E2, H2, TH1_2, TH3_2);
    spmm_final_kernel<<<SPMM_BLKS, TPB>>>(out, TH1_3, TH3_3);
}